// round 16
// baseline (speedup 1.0000x reference)
// LSTM cell fused GEMM on sm_103 baseline ISA, fp16 mma.sync.m16n8k16.
// R16 = R13 (single fused cvt; all-warps-produce, 4x 64x64 warp tiles,
// 2 CTA/SM, mbarrier pipeline, interleaved ks blocks, precomputed producer
// addressing) + SPLIT PRODUCER BURST:
//   stage top:        empty-wait (relaxed) + 8 A-tile cp.asyncs
//   after ksblock(0): 8 B-tile cp.asyncs + cp.async mbarrier arrive
// Half the 16-deep LDGSTS issue burst now drains under 32 in-flight MMAs
// instead of stalling the tensor pipe ahead of ks0.

#include <cuda_runtime.h>
#include <cuda_fp16.h>
#include <cstdint>

#define DEVINL __device__ __forceinline__

constexpr int BATCH = 4096;
constexpr int SZ    = 2048;
constexpr int TM    = 128;               // batch tile
constexpr int TOG   = 32;                // per-gate feature tile
constexpr int TN    = 128;               // 4 gates * TOG
constexpr int KS    = 64;                // K halfs per stage (128 B rows)
constexpr int NS    = (2 * SZ) / KS;     // 64 stages
constexpr int NBUF  = 3;
constexpr int NTHR  = 128;               // 4 warps
constexpr int ABYTES = TM * KS * 2;      // 16 KB
constexpr int BBYTES = TN * KS * 2;      // 16 KB
constexpr int STAGE_BYTES = ABYTES + BBYTES;   // 32 KB
constexpr int SM_BIAS = NBUF * STAGE_BYTES;    // 98304
constexpr int SM_MBAR = SM_BIAS + TN * 4;      // 98816
constexpr int SMEM_TOTAL = SM_MBAR + 64;       // 98880 (2 CTA/SM fits)
constexpr int EPS = 130;                 // epilogue smem row stride (floats)

// fp16 scratch: [x | h | Wx | Wh]
constexpr size_t OFF_X  = 0;
constexpr size_t OFF_H  = (size_t)BATCH * SZ;
constexpr size_t OFF_WX = OFF_H + (size_t)BATCH * SZ;
constexpr size_t OFF_WH = OFF_WX + (size_t)4 * SZ * SZ;
constexpr size_t SCRATCH_ELEMS = OFF_WH + (size_t)4 * SZ * SZ;
__device__ __half g_scratch[SCRATCH_ELEMS];

constexpr int ACT4 = BATCH * SZ / 4;
constexpr int W4   = 4 * SZ * SZ / 4;
constexpr int TOT4 = 2 * ACT4 + 2 * W4;

DEVINL uint32_t smem_u32(const void* p) {
  uint32_t r;
  asm("{ .reg .u64 t; cvta.to.shared.u64 t, %1; cvt.u32.u64 %0, t; }"
      : "=r"(r) : "l"(p));
  return r;
}
DEVINL uint32_t swz(uint32_t b) { return b ^ ((b >> 3) & 0x70); }

DEVINL void cp16(uint32_t dst, const void* src) {
  asm volatile("cp.async.cg.shared.global [%0], [%1], 16;"
               :: "r"(dst), "l"(src));
}
DEVINL void cp_arrive_noinc(uint32_t mbar) {
  asm volatile("cp.async.mbarrier.arrive.noinc.shared.b64 [%0];"
               :: "r"(mbar) : "memory");
}
DEVINL void mbar_init(uint32_t mbar, uint32_t cnt) {
  asm volatile("mbarrier.init.shared.b64 [%0], %1;" :: "r"(mbar), "r"(cnt)
               : "memory");
}
DEVINL void mbar_arrive(uint32_t mbar) {
  asm volatile("mbarrier.arrive.release.cta.shared::cta.b64 _, [%0];"
               :: "r"(mbar) : "memory");
}
DEVINL void mbar_wait(uint32_t mbar, uint32_t parity) {
  asm volatile(
      "{\n\t.reg .pred P;\n"
      "W%=:\n\t"
      "mbarrier.try_wait.parity.acquire.cta.shared::cta.b64 P, [%0], %1, 0x989680;\n\t"
      "@!P bra W%=;\n\t}"
      :: "r"(mbar), "r"(parity) : "memory");
}
// Relaxed: ONLY the producer's empty-wait (post-wait = async-proxy writes).
DEVINL void mbar_wait_relaxed(uint32_t mbar, uint32_t parity) {
  asm volatile(
      "{\n\t.reg .pred P;\n"
      "W%=:\n\t"
      "mbarrier.try_wait.parity.relaxed.cta.shared::cta.b64 P, [%0], %1, 0x989680;\n\t"
      "@!P bra W%=;\n\t}"
      :: "r"(mbar), "r"(parity) : "memory");
}

// Volatile: ordering vs mbarrier waits is positional.
DEVINL void ldsm4(uint32_t* r, uint32_t addr) {
  asm volatile(
      "ldmatrix.sync.aligned.m8n8.x4.shared.b16 {%0,%1,%2,%3}, [%4];"
      : "=r"(r[0]), "=r"(r[1]), "=r"(r[2]), "=r"(r[3]) : "r"(addr));
}
// Non-volatile: ptxas may schedule MMAs freely to fill wait windows.
DEVINL void mma16(float* d, const uint32_t* a, const uint32_t* b) {
  asm("mma.sync.aligned.m16n8k16.row.col.f32.f16.f16.f32 "
      "{%0,%1,%2,%3}, {%4,%5,%6,%7}, {%8,%9}, {%0,%1,%2,%3};"
      : "+f"(d[0]), "+f"(d[1]), "+f"(d[2]), "+f"(d[3])
      : "r"(a[0]), "r"(a[1]), "r"(a[2]), "r"(a[3]), "r"(b[0]), "r"(b[1]));
}

DEVINL float sigmoidf_(float x) { return __fdividef(1.f, 1.f + __expf(-x)); }
DEVINL float tanhf_(float x) {
  float a = fabsf(x);
  float e = __expf(-2.f * a);
  return copysignf(__fdividef(1.f - e, 1.f + e), x);
}

// ---- Phase 1: fp32 -> fp16, 4 float4 per thread (MLP=4), single kernel ----
__global__ void __launch_bounds__(256)
cvt_all_kernel(const float* __restrict__ x, const float* __restrict__ h,
               const float* __restrict__ wx, const float* __restrict__ wh) {
  int q = blockIdx.x * 256 + threadIdx.x;   // quad index
  int i = q * 4;                            // global float4 index
  const float* src;
  int base;
  if (i < ACT4)               { src = x;  base = 0; }
  else if (i < 2 * ACT4)      { src = h;  base = ACT4; }
  else if (i < 2 * ACT4 + W4) { src = wx; base = 2 * ACT4; }
  else                        { src = wh; base = 2 * ACT4 + W4; }
  const float4* sp = (const float4*)src + (i - base);
  float4 v0 = sp[0], v1 = sp[1], v2 = sp[2], v3 = sp[3];
  uint4 o0, o1;
  __half2 t;
  t = __floats2half2_rn(v0.x, v0.y); o0.x = *(uint32_t*)&t;
  t = __floats2half2_rn(v0.z, v0.w); o0.y = *(uint32_t*)&t;
  t = __floats2half2_rn(v1.x, v1.y); o0.z = *(uint32_t*)&t;
  t = __floats2half2_rn(v1.z, v1.w); o0.w = *(uint32_t*)&t;
  t = __floats2half2_rn(v2.x, v2.y); o1.x = *(uint32_t*)&t;
  t = __floats2half2_rn(v2.z, v2.w); o1.y = *(uint32_t*)&t;
  t = __floats2half2_rn(v3.x, v3.y); o1.z = *(uint32_t*)&t;
  t = __floats2half2_rn(v3.z, v3.w); o1.w = *(uint32_t*)&t;
  ((uint4*)g_scratch)[2 * (size_t)q]     = o0;
  ((uint4*)g_scratch)[2 * (size_t)q + 1] = o1;
}

// ---- Phase 2: fused GEMM + LSTM epilogue, mbarrier-pipelined ----
__global__ void __launch_bounds__(NTHR, 2)
lstm_kernel(const float* __restrict__ c, const float* __restrict__ bx,
            const float* __restrict__ bh, float* __restrict__ out) {
  extern __shared__ char smem[];
  const uint32_t sb = smem_u32(smem);
  const int tid = threadIdx.x;
  const int lane = tid & 31;
  const int wid = tid >> 5;            // 0..3
  const int m0 = blockIdx.x * TM;
  const int o0 = blockIdx.y * TOG;
  const int warp_m = (wid >> 1) * 64;  // 2 warps along M
  const int warp_n = (wid & 1) * 64;   // 2 warps along N

  if (tid == 0) {
#pragma unroll
    for (int b = 0; b < NBUF; ++b) {
      mbar_init(sb + SM_MBAR + b * 16, NTHR);    // full: one per thread
      mbar_init(sb + SM_MBAR + b * 16 + 8, 4);   // empty: one per warp
    }
  }
  float* bias_sm = (float*)(smem + SM_BIAS);
  if (tid < TN) {
    int g = tid >> 5, o = o0 + (tid & 31);
    bias_sm[tid] = bx[g * SZ + o] + bh[g * SZ + o];
  }
  __syncthreads();

  // ldmatrix lane geometry.
  const int a_r  = lane & 15;
  const int a_c  = (lane & 16) ? 16 : 0;
  const int b_r  = (lane & 7) | ((lane & 16) >> 1);
  const int b_c  = (lane & 8) ? 16 : 0;

  // ---- Precomputed producer addressing (R13) ----
  const int r0 = tid >> 3;             // 0..15
  const int cc = tid & 7;              // 16-B column
  uint32_t wsw[8];                     // swizzled smem write offsets (A==B)
#pragma unroll
  for (int j = 0; j < 8; ++j)
    wsw[j] = swz((uint32_t)((r0 + 16 * j) * 128 + cc * 16));
  const __half* aput = g_scratch + OFF_X + (size_t)(m0 + r0) * SZ + cc * 8;
  const __half* bput = g_scratch + OFF_WX + (size_t)(o0 + r0) * SZ + cc * 8;
  constexpr size_t DA = OFF_H - OFF_X;     // x -> h
  constexpr size_t DW = OFF_WH - OFF_WX;   // Wx -> Wh
  constexpr size_t BG = (size_t)SZ * SZ;   // gate stride in W
  constexpr size_t BR = (size_t)16 * SZ;   // 16-row stride

  int pstage = 0, pphase = 1;     // producer cursor (first 3 waits pass)
  int cstage = 0, cphase = 0;     // consumer cursor
  // Producer state carried between the A-half and B-half of a stage.
  uint32_t p_mb = 0, p_ab = 0;
  const __half* p_bp = nullptr;

  // A-half: empty-wait + 8 A-tile cp.asyncs. Sets p_* for the B-half.
  auto produceA = [&](int s) {
    const size_t ph_a = (s < NS / 2) ? 0 : DA;
    const size_t ph_w = (s < NS / 2) ? 0 : DW;
    const int k0 = (s & (NS / 2 - 1)) * KS;
    p_mb = sb + SM_MBAR + pstage * 16;
    mbar_wait_relaxed(p_mb + 8, (uint32_t)pphase);  // buffer free?
    p_ab = sb + pstage * STAGE_BYTES;
    const __half* ap = aput + ph_a + k0;
    p_bp = bput + ph_w + k0;
#pragma unroll
    for (int j = 0; j < 8; ++j)
      cp16(p_ab + wsw[j], ap + (size_t)j * BR);
    if (++pstage == NBUF) { pstage = 0; pphase ^= 1; }
  };
  // B-half: 8 B-tile cp.asyncs + arrive (after ksblock(0)'s MMAs issued).
  auto produceB = [&]() {
    const uint32_t bb = p_ab + ABYTES;
#pragma unroll
    for (int j = 0; j < 8; ++j)
      cp16(bb + wsw[j], p_bp + (size_t)(j >> 1) * BG + (size_t)(j & 1) * BR);
    cp_arrive_noinc(p_mb);
  };

  float acc[4][8][4];
#pragma unroll
  for (int i = 0; i < 4; ++i)
#pragma unroll
    for (int j = 0; j < 8; ++j)
#pragma unroll
      for (int e = 0; e < 4; ++e) acc[i][j][e] = 0.f;

  // One ks block, explicitly interleaved (R12/R13 form — best measured).
  auto ksblock = [&](int ks, uint32_t ab, uint32_t bb, uint32_t rel_mbar) {
    const uint32_t kc = (uint32_t)ks * 32;
    uint32_t af[4][4], bq[4][4];
    ldsm4(bq[0], bb + swz((uint32_t)((warp_n + b_r) * 128 + kc + b_c)));
#pragma unroll
    for (int mt = 0; mt < 4; ++mt)
      ldsm4(af[mt],
            ab + swz((uint32_t)((warp_m + mt * 16 + a_r) * 128 + kc + a_c)));
#pragma unroll
    for (int nt = 0; nt < 2; ++nt)
#pragma unroll
      for (int mt = 0; mt < 4; ++mt)
        mma16(acc[mt][nt], af[mt], &bq[0][(nt & 1) * 2]);
#pragma unroll
    for (int np = 1; np < 4; ++np) {
      ldsm4(bq[np],
            bb + swz((uint32_t)((warp_n + np * 16 + b_r) * 128 + kc + b_c)));
      if (np == 3 && rel_mbar && lane == 0) mbar_arrive(rel_mbar);
#pragma unroll
      for (int nt = 2 * np; nt < 2 * np + 2; ++nt)
#pragma unroll
        for (int mt = 0; mt < 4; ++mt)
          mma16(acc[mt][nt], af[mt], &bq[np][(nt & 1) * 2]);
    }
  };

  // Prologue: fully produce stages 0 and 1 (A+B contiguous — no MMAs yet).
  produceA(0); produceB();
  produceA(1); produceB();

  for (int s = 0; s < NS; ++s) {
    const bool pre = (s + 2 < NS);
    if (pre) produceA(s + 2);           // A-half ahead of the full-wait
    const uint32_t mb = sb + SM_MBAR + cstage * 16;
    mbar_wait(mb, (uint32_t)cphase);
    const uint32_t ab = sb + cstage * STAGE_BYTES;
    const uint32_t bb = ab + ABYTES;
    ksblock(0, ab, bb, 0u);
    if (pre) produceB();                // B-half under 32 in-flight MMAs
#pragma unroll
    for (int ks = 1; ks < 4; ++ks)
      ksblock(ks, ab, bb, (ks == 3) ? (mb + 8) : 0u);
    if (++cstage == NBUF) { cstage = 0; cphase ^= 1; }
  }

  // Epilogue: regather all 4 gates per (b, o) through smem.
  __syncthreads();
  float* ep = (float*)smem;  // [128][EPS]
#pragma unroll
  for (int mt = 0; mt < 4; ++mt)
#pragma unroll
    for (int nt = 0; nt < 8; ++nt) {
      int row = warp_m + mt * 16 + (lane >> 2);
      int col = warp_n + nt * 8 + 2 * (lane & 3);
      ep[row * EPS + col]           = acc[mt][nt][0];
      ep[row * EPS + col + 1]       = acc[mt][nt][1];
      ep[(row + 8) * EPS + col]     = acc[mt][nt][2];
      ep[(row + 8) * EPS + col + 1] = acc[mt][nt][3];
    }
  __syncthreads();

#pragma unroll 1
  for (int p = 0; p < 32; ++p) {
    int idx = tid + p * NTHR;         // 128*32 outputs per CTA
    int b = idx >> 5, o = idx & 31;
    float gi = ep[b * EPS + 0 * 32 + o] + bias_sm[0 * 32 + o];
    float gf = ep[b * EPS + 1 * 32 + o] + bias_sm[1 * 32 + o];
    float go = ep[b * EPS + 2 * 32 + o] + bias_sm[2 * 32 + o];
    float gc = ep[b * EPS + 3 * 32 + o] + bias_sm[3 * 32 + o];
    size_t gidx = (size_t)(m0 + b) * SZ + (o0 + o);
    float cv = c[gidx];
    float iv = sigmoidf_(gi), fv = sigmoidf_(gf), ov = sigmoidf_(go);
    float cand = tanhf_(gc);
    float cn = fv * cv + iv * cand;
    out[gidx] = ov * tanhf_(cn);
    out[(size_t)BATCH * SZ + gidx] = cn;
  }
}

extern "C" void kernel_launch(void* const* d_in, const int* in_sizes, int n_in,
                              void* d_out, int out_size) {
  (void)in_sizes; (void)n_in; (void)out_size;
  const float* x  = (const float*)d_in[0];
  const float* h  = (const float*)d_in[1];
  const float* c  = (const float*)d_in[2];
  const float* Wx = (const float*)d_in[3];
  const float* bx = (const float*)d_in[4];
  const float* Wh = (const float*)d_in[5];
  const float* bh = (const float*)d_in[6];

  cvt_all_kernel<<<TOT4 / 4 / 256, 256>>>(x, h, Wx, Wh);

  cudaFuncSetAttribute(lstm_kernel, cudaFuncAttributeMaxDynamicSharedMemorySize,
                       SMEM_TOTAL);
  dim3 grid(BATCH / TM, SZ / TOG, 1);
  lstm_kernel<<<grid, NTHR, SMEM_TOTAL>>>(c, bx, bh, (float*)d_out);
}

// round 17
// speedup vs baseline: 1.0858x; 1.0858x over previous
// LSTM cell fused GEMM on sm_103 baseline ISA, fp16 mma.sync.m16n8k16.
// R17 = R13 mainloop VERBATIM (best measured: all-warps-produce, 4x 64x64
// warp tiles, 2 CTA/SM, mbarrier pipeline, interleaved ks blocks,
// precomputed producer addressing, single fused MLP=4 cvt) +
// VECTORIZED EPILOGUE: EPS 130 -> 132 (16B-aligned rows, conflict-free
// LDS.128 phases), 4 features per thread-iteration: 8 iterations of
// float4 LDS/LDG/STG instead of 32 scalar ones.

#include <cuda_runtime.h>
#include <cuda_fp16.h>
#include <cstdint>

#define DEVINL __device__ __forceinline__

constexpr int BATCH = 4096;
constexpr int SZ    = 2048;
constexpr int TM    = 128;               // batch tile
constexpr int TOG   = 32;                // per-gate feature tile
constexpr int TN    = 128;               // 4 gates * TOG
constexpr int KS    = 64;                // K halfs per stage (128 B rows)
constexpr int NS    = (2 * SZ) / KS;     // 64 stages
constexpr int NBUF  = 3;
constexpr int NTHR  = 128;               // 4 warps
constexpr int ABYTES = TM * KS * 2;      // 16 KB
constexpr int BBYTES = TN * KS * 2;      // 16 KB
constexpr int STAGE_BYTES = ABYTES + BBYTES;   // 32 KB
constexpr int SM_BIAS = NBUF * STAGE_BYTES;    // 98304
constexpr int SM_MBAR = SM_BIAS + TN * 4;      // 98816
constexpr int SMEM_TOTAL = SM_MBAR + 64;       // 98880 (2 CTA/SM fits)
constexpr int EPS = 132;                 // epilogue row stride (floats, /4)

// fp16 scratch: [x | h | Wx | Wh]
constexpr size_t OFF_X  = 0;
constexpr size_t OFF_H  = (size_t)BATCH * SZ;
constexpr size_t OFF_WX = OFF_H + (size_t)BATCH * SZ;
constexpr size_t OFF_WH = OFF_WX + (size_t)4 * SZ * SZ;
constexpr size_t SCRATCH_ELEMS = OFF_WH + (size_t)4 * SZ * SZ;
__device__ __half g_scratch[SCRATCH_ELEMS];

constexpr int ACT4 = BATCH * SZ / 4;
constexpr int W4   = 4 * SZ * SZ / 4;
constexpr int TOT4 = 2 * ACT4 + 2 * W4;

DEVINL uint32_t smem_u32(const void* p) {
  uint32_t r;
  asm("{ .reg .u64 t; cvta.to.shared.u64 t, %1; cvt.u32.u64 %0, t; }"
      : "=r"(r) : "l"(p));
  return r;
}
DEVINL uint32_t swz(uint32_t b) { return b ^ ((b >> 3) & 0x70); }

DEVINL void cp16(uint32_t dst, const void* src) {
  asm volatile("cp.async.cg.shared.global [%0], [%1], 16;"
               :: "r"(dst), "l"(src));
}
DEVINL void cp_arrive_noinc(uint32_t mbar) {
  asm volatile("cp.async.mbarrier.arrive.noinc.shared.b64 [%0];"
               :: "r"(mbar) : "memory");
}
DEVINL void mbar_init(uint32_t mbar, uint32_t cnt) {
  asm volatile("mbarrier.init.shared.b64 [%0], %1;" :: "r"(mbar), "r"(cnt)
               : "memory");
}
DEVINL void mbar_arrive(uint32_t mbar) {
  asm volatile("mbarrier.arrive.release.cta.shared::cta.b64 _, [%0];"
               :: "r"(mbar) : "memory");
}
DEVINL void mbar_wait(uint32_t mbar, uint32_t parity) {
  asm volatile(
      "{\n\t.reg .pred P;\n"
      "W%=:\n\t"
      "mbarrier.try_wait.parity.acquire.cta.shared::cta.b64 P, [%0], %1, 0x989680;\n\t"
      "@!P bra W%=;\n\t}"
      :: "r"(mbar), "r"(parity) : "memory");
}
// Relaxed: ONLY the producer's empty-wait (post-wait = async-proxy writes).
DEVINL void mbar_wait_relaxed(uint32_t mbar, uint32_t parity) {
  asm volatile(
      "{\n\t.reg .pred P;\n"
      "W%=:\n\t"
      "mbarrier.try_wait.parity.relaxed.cta.shared::cta.b64 P, [%0], %1, 0x989680;\n\t"
      "@!P bra W%=;\n\t}"
      :: "r"(mbar), "r"(parity) : "memory");
}

// Volatile: ordering vs mbarrier waits is positional.
DEVINL void ldsm4(uint32_t* r, uint32_t addr) {
  asm volatile(
      "ldmatrix.sync.aligned.m8n8.x4.shared.b16 {%0,%1,%2,%3}, [%4];"
      : "=r"(r[0]), "=r"(r[1]), "=r"(r[2]), "=r"(r[3]) : "r"(addr));
}
// Non-volatile: ptxas may schedule MMAs freely to fill wait windows.
DEVINL void mma16(float* d, const uint32_t* a, const uint32_t* b) {
  asm("mma.sync.aligned.m16n8k16.row.col.f32.f16.f16.f32 "
      "{%0,%1,%2,%3}, {%4,%5,%6,%7}, {%8,%9}, {%0,%1,%2,%3};"
      : "+f"(d[0]), "+f"(d[1]), "+f"(d[2]), "+f"(d[3])
      : "r"(a[0]), "r"(a[1]), "r"(a[2]), "r"(a[3]), "r"(b[0]), "r"(b[1]));
}

DEVINL float sigmoidf_(float x) { return __fdividef(1.f, 1.f + __expf(-x)); }
DEVINL float tanhf_(float x) {
  float a = fabsf(x);
  float e = __expf(-2.f * a);
  return copysignf(__fdividef(1.f - e, 1.f + e), x);
}

// ---- Phase 1: fp32 -> fp16, 4 float4 per thread (MLP=4), single kernel ----
__global__ void __launch_bounds__(256)
cvt_all_kernel(const float* __restrict__ x, const float* __restrict__ h,
               const float* __restrict__ wx, const float* __restrict__ wh) {
  int q = blockIdx.x * 256 + threadIdx.x;   // quad index
  int i = q * 4;                            // global float4 index
  const float* src;
  int base;
  if (i < ACT4)               { src = x;  base = 0; }
  else if (i < 2 * ACT4)      { src = h;  base = ACT4; }
  else if (i < 2 * ACT4 + W4) { src = wx; base = 2 * ACT4; }
  else                        { src = wh; base = 2 * ACT4 + W4; }
  const float4* sp = (const float4*)src + (i - base);
  float4 v0 = sp[0], v1 = sp[1], v2 = sp[2], v3 = sp[3];
  uint4 o0, o1;
  __half2 t;
  t = __floats2half2_rn(v0.x, v0.y); o0.x = *(uint32_t*)&t;
  t = __floats2half2_rn(v0.z, v0.w); o0.y = *(uint32_t*)&t;
  t = __floats2half2_rn(v1.x, v1.y); o0.z = *(uint32_t*)&t;
  t = __floats2half2_rn(v1.z, v1.w); o0.w = *(uint32_t*)&t;
  t = __floats2half2_rn(v2.x, v2.y); o1.x = *(uint32_t*)&t;
  t = __floats2half2_rn(v2.z, v2.w); o1.y = *(uint32_t*)&t;
  t = __floats2half2_rn(v3.x, v3.y); o1.z = *(uint32_t*)&t;
  t = __floats2half2_rn(v3.z, v3.w); o1.w = *(uint32_t*)&t;
  ((uint4*)g_scratch)[2 * (size_t)q]     = o0;
  ((uint4*)g_scratch)[2 * (size_t)q + 1] = o1;
}

// ---- Phase 2: fused GEMM + LSTM epilogue, mbarrier-pipelined ----
__global__ void __launch_bounds__(NTHR, 2)
lstm_kernel(const float* __restrict__ c, const float* __restrict__ bx,
            const float* __restrict__ bh, float* __restrict__ out) {
  extern __shared__ char smem[];
  const uint32_t sb = smem_u32(smem);
  const int tid = threadIdx.x;
  const int lane = tid & 31;
  const int wid = tid >> 5;            // 0..3
  const int m0 = blockIdx.x * TM;
  const int o0 = blockIdx.y * TOG;
  const int warp_m = (wid >> 1) * 64;  // 2 warps along M
  const int warp_n = (wid & 1) * 64;   // 2 warps along N

  if (tid == 0) {
#pragma unroll
    for (int b = 0; b < NBUF; ++b) {
      mbar_init(sb + SM_MBAR + b * 16, NTHR);    // full: one per thread
      mbar_init(sb + SM_MBAR + b * 16 + 8, 4);   // empty: one per warp
    }
  }
  float* bias_sm = (float*)(smem + SM_BIAS);
  if (tid < TN) {
    int g = tid >> 5, o = o0 + (tid & 31);
    bias_sm[tid] = bx[g * SZ + o] + bh[g * SZ + o];
  }
  __syncthreads();

  // ldmatrix lane geometry.
  const int a_r  = lane & 15;
  const int a_c  = (lane & 16) ? 16 : 0;
  const int b_r  = (lane & 7) | ((lane & 16) >> 1);
  const int b_c  = (lane & 8) ? 16 : 0;

  // ---- Precomputed producer addressing (R13) ----
  const int r0 = tid >> 3;             // 0..15
  const int cc = tid & 7;              // 16-B column
  uint32_t wsw[8];                     // swizzled smem write offsets (A==B)
#pragma unroll
  for (int j = 0; j < 8; ++j)
    wsw[j] = swz((uint32_t)((r0 + 16 * j) * 128 + cc * 16));
  const __half* aput = g_scratch + OFF_X + (size_t)(m0 + r0) * SZ + cc * 8;
  const __half* bput = g_scratch + OFF_WX + (size_t)(o0 + r0) * SZ + cc * 8;
  constexpr size_t DA = OFF_H - OFF_X;     // x -> h
  constexpr size_t DW = OFF_WH - OFF_WX;   // Wx -> Wh
  constexpr size_t BG = (size_t)SZ * SZ;   // gate stride in W
  constexpr size_t BR = (size_t)16 * SZ;   // 16-row stride

  int pstage = 0, pphase = 1;     // producer cursor (first 3 waits pass)
  int cstage = 0, cphase = 0;     // consumer cursor
  auto produce = [&](int s) {
    const size_t ph_a = (s < NS / 2) ? 0 : DA;
    const size_t ph_w = (s < NS / 2) ? 0 : DW;
    const int k0 = (s & (NS / 2 - 1)) * KS;
    const uint32_t mb = sb + SM_MBAR + pstage * 16;
    mbar_wait_relaxed(mb + 8, (uint32_t)pphase);  // buffer free?
    const uint32_t ab = sb + pstage * STAGE_BYTES;
    const uint32_t bb = ab + ABYTES;
    const __half* ap = aput + ph_a + k0;
    const __half* bp = bput + ph_w + k0;
#pragma unroll
    for (int j = 0; j < 8; ++j)                    // A: immediates per j
      cp16(ab + wsw[j], ap + (size_t)j * BR);
#pragma unroll
    for (int j = 0; j < 8; ++j)                    // B: gate = j>>1
      cp16(bb + wsw[j], bp + (size_t)(j >> 1) * BG + (size_t)(j & 1) * BR);
    cp_arrive_noinc(mb);
    if (++pstage == NBUF) { pstage = 0; pphase ^= 1; }
  };

  float acc[4][8][4];
#pragma unroll
  for (int i = 0; i < 4; ++i)
#pragma unroll
    for (int j = 0; j < 8; ++j)
#pragma unroll
      for (int e = 0; e < 4; ++e) acc[i][j][e] = 0.f;

  // One ks block, explicitly interleaved (R12/R13 form — best measured).
  auto ksblock = [&](int ks, uint32_t ab, uint32_t bb, uint32_t rel_mbar) {
    const uint32_t kc = (uint32_t)ks * 32;
    uint32_t af[4][4], bq[4][4];
    ldsm4(bq[0], bb + swz((uint32_t)((warp_n + b_r) * 128 + kc + b_c)));
#pragma unroll
    for (int mt = 0; mt < 4; ++mt)
      ldsm4(af[mt],
            ab + swz((uint32_t)((warp_m + mt * 16 + a_r) * 128 + kc + a_c)));
#pragma unroll
    for (int nt = 0; nt < 2; ++nt)
#pragma unroll
      for (int mt = 0; mt < 4; ++mt)
        mma16(acc[mt][nt], af[mt], &bq[0][(nt & 1) * 2]);
#pragma unroll
    for (int np = 1; np < 4; ++np) {
      ldsm4(bq[np],
            bb + swz((uint32_t)((warp_n + np * 16 + b_r) * 128 + kc + b_c)));
      if (np == 3 && rel_mbar && lane == 0) mbar_arrive(rel_mbar);
#pragma unroll
      for (int nt = 2 * np; nt < 2 * np + 2; ++nt)
#pragma unroll
        for (int mt = 0; mt < 4; ++mt)
          mma16(acc[mt][nt], af[mt], &bq[np][(nt & 1) * 2]);
    }
  };

  produce(0);
  produce(1);

  for (int s = 0; s < NS; ++s) {
    if (s + 2 < NS) produce(s + 2);
    const uint32_t mb = sb + SM_MBAR + cstage * 16;
    mbar_wait(mb, (uint32_t)cphase);
    const uint32_t ab = sb + cstage * STAGE_BYTES;
    const uint32_t bb = ab + ABYTES;
#pragma unroll
    for (int ks = 0; ks < 4; ++ks)
      ksblock(ks, ab, bb, (ks == 3) ? (mb + 8) : 0u);
    if (++cstage == NBUF) { cstage = 0; cphase ^= 1; }
  }

  // Epilogue: regather all 4 gates per (b, o) through smem — vectorized.
  __syncthreads();
  float* ep = (float*)smem;  // [128][EPS], EPS=132 (16B-aligned rows)
#pragma unroll
  for (int mt = 0; mt < 4; ++mt)
#pragma unroll
    for (int nt = 0; nt < 8; ++nt) {
      int row = warp_m + mt * 16 + (lane >> 2);
      int col = warp_n + nt * 8 + 2 * (lane & 3);
      ep[row * EPS + col]           = acc[mt][nt][0];
      ep[row * EPS + col + 1]       = acc[mt][nt][1];
      ep[(row + 8) * EPS + col]     = acc[mt][nt][2];
      ep[(row + 8) * EPS + col + 1] = acc[mt][nt][3];
    }
  __syncthreads();

  // 4 consecutive features per iteration: 8 iterations of float4 traffic.
#pragma unroll 1
  for (int p = 0; p < 8; ++p) {
    int idx = tid + p * NTHR;         // 1024 quads per CTA (128 rows x 8)
    int b  = idx >> 3;                // batch row within tile
    int o4 = (idx & 7) * 4;           // feature quad origin (0..28)
    const float* er = ep + b * EPS;
    float4 g0 = *(const float4*)(er + 0 * 32 + o4);
    float4 g1 = *(const float4*)(er + 1 * 32 + o4);
    float4 g2 = *(const float4*)(er + 2 * 32 + o4);
    float4 g3 = *(const float4*)(er + 3 * 32 + o4);
    float4 b0 = *(const float4*)(bias_sm + 0 * 32 + o4);
    float4 b1 = *(const float4*)(bias_sm + 1 * 32 + o4);
    float4 b2 = *(const float4*)(bias_sm + 2 * 32 + o4);
    float4 b3 = *(const float4*)(bias_sm + 3 * 32 + o4);
    size_t gidx = (size_t)(m0 + b) * SZ + (o0 + o4);
    float4 cv4 = *(const float4*)(c + gidx);
    float hn[4], cn[4];
    const float* gi = (const float*)&g0; const float* bi = (const float*)&b0;
    const float* gf = (const float*)&g1; const float* bf = (const float*)&b1;
    const float* go = (const float*)&g2; const float* bo = (const float*)&b2;
    const float* gc = (const float*)&g3; const float* bc = (const float*)&b3;
    const float* cf = (const float*)&cv4;
#pragma unroll
    for (int j = 0; j < 4; ++j) {
      float iv = sigmoidf_(gi[j] + bi[j]);
      float fv = sigmoidf_(gf[j] + bf[j]);
      float ov = sigmoidf_(go[j] + bo[j]);
      float cand = tanhf_(gc[j] + bc[j]);
      float cnv = fv * cf[j] + iv * cand;
      cn[j] = cnv;
      hn[j] = ov * tanhf_(cnv);
    }
    *(float4*)(out + gidx) = make_float4(hn[0], hn[1], hn[2], hn[3]);
    *(float4*)(out + (size_t)BATCH * SZ + gidx) =
        make_float4(cn[0], cn[1], cn[2], cn[3]);
  }
}

extern "C" void kernel_launch(void* const* d_in, const int* in_sizes, int n_in,
                              void* d_out, int out_size) {
  (void)in_sizes; (void)n_in; (void)out_size;
  const float* x  = (const float*)d_in[0];
  const float* h  = (const float*)d_in[1];
  const float* c  = (const float*)d_in[2];
  const float* Wx = (const float*)d_in[3];
  const float* bx = (const float*)d_in[4];
  const float* Wh = (const float*)d_in[5];
  const float* bh = (const float*)d_in[6];

  cvt_all_kernel<<<TOT4 / 4 / 256, 256>>>(x, h, Wx, Wh);

  cudaFuncSetAttribute(lstm_kernel, cudaFuncAttributeMaxDynamicSharedMemorySize,
                       SMEM_TOTAL);
  dim3 grid(BATCH / TM, SZ / TOG, 1);
  lstm_kernel<<<grid, NTHR, SMEM_TOTAL>>>(c, bx, bh, (float*)d_out);
}